// round 8
// baseline (speedup 1.0000x reference)
#include <cuda_runtime.h>
#include <cstdint>

// Problem constants
#define N_IMG 16384
#define SS 49
#define NCELL (N_IMG * SS)              // 802816
#define F 30
#define CPC 64                          // cells per chunk
#define NCHUNK (NCELL / CPC)            // 12544
#define THREADS 128                     // 2 threads per cell (pair-split)
#define GRID 444                        // 3 blocks/SM * 148 SMs
#define STAGES 4

#define CHUNK_FLOATS (CPC * F)          // 1920 floats per tensor
#define CHUNK_BYTES (CHUNK_FLOATS * 4)  // 7680 B per tensor
#define TX_BYTES (2 * CHUNK_BYTES)      // 15360 B per chunk
#define DYN_SMEM (STAGES * TX_BYTES)    // 61440 B

__device__ float g_partial[GRID];
__device__ unsigned int g_count;        // zero at load; last block resets each run
__device__ unsigned int g_ticket;       // dynamic chunk scheduler; reset each run

__device__ __forceinline__ uint32_t smem_u32(const void* p) {
    return (uint32_t)__cvta_generic_to_shared(p);
}

#define MBAR_WAIT(bar, parity) do {                                           \
    asm volatile(                                                             \
        "{\n\t.reg .pred P1;\n\t"                                             \
        "WAIT_%=:\n\t"                                                        \
        "mbarrier.try_wait.parity.acquire.cta.shared::cta.b64 P1, [%0], %1, 0x989680;\n\t" \
        "@P1 bra.uni DONE_%=;\n\t"                                            \
        "bra.uni WAIT_%=;\n\t"                                                \
        "DONE_%=:\n\t}"                                                       \
        :: "r"(bar), "r"(parity) : "memory");                                 \
} while (0)

__global__ __launch_bounds__(THREADS) void loss_kernel(
        const float* __restrict__ preds,
        const float* __restrict__ targets,
        float* __restrict__ out) {
    extern __shared__ float smem[];     // [STAGES][preds 1920 | targets 1920]
    __shared__ __align__(8) unsigned long long mbar[STAGES];
    __shared__ int s_chunk[STAGES];
    __shared__ float warp_sums[THREADS / 32];
    __shared__ double dsum[THREADS / 32];
    __shared__ bool is_last;

    const int tid = threadIdx.x;
    const int part = tid & 1;           // 0: classes 0-9 + box0; 1: classes 10-19 + box1
    const int cell = tid >> 1;          // 0..63 within chunk

    if (tid == 0) {
#pragma unroll
        for (int s = 0; s < STAGES; s++)
            asm volatile("mbarrier.init.shared.b64 [%0], 1;"
                         :: "r"(smem_u32(&mbar[s])) : "memory");
    }
    __syncthreads();

    auto issue = [&](int c, int buf) {
        uint32_t bar = smem_u32(&mbar[buf]);
        asm volatile("mbarrier.arrive.expect_tx.shared.b64 _, [%0], %1;"
                     :: "r"(bar), "r"((uint32_t)TX_BYTES) : "memory");
        uint32_t dstp = smem_u32(smem) + buf * TX_BYTES;
        uint32_t dstt = dstp + CHUNK_BYTES;
        const float* srcp = preds + (long long)c * CHUNK_FLOATS;
        const float* srct = targets + (long long)c * CHUNK_FLOATS;
        asm volatile("cp.async.bulk.shared::cta.global.mbarrier::complete_tx::bytes [%0], [%1], %2, [%3];"
                     :: "r"(dstp), "l"(srcp), "r"((uint32_t)CHUNK_BYTES), "r"(bar) : "memory");
        asm volatile("cp.async.bulk.shared::cta.global.mbarrier::complete_tx::bytes [%0], [%1], %2, [%3];"
                     :: "r"(dstt), "l"(srct), "r"((uint32_t)CHUNK_BYTES), "r"(bar) : "memory");
    };

    // Prologue: grab and issue chunks into stages 0..2 (stage 3 filled in-loop).
    if (tid == 0) {
#pragma unroll
        for (int s = 0; s < STAGES - 1; s++) {
            int c = (int)atomicAdd(&g_ticket, 1u);
            s_chunk[s] = c;
            if (c < NCHUNK) issue(c, s);
        }
        s_chunk[STAGES - 1] = 0;        // placeholder; written before first read
    }
    __syncthreads();

    float l = 0.0f;
    int buf = 0, phs = 0;
    for (;;) {
        const int c = s_chunk[buf];
        if (c >= NCHUNK) break;
        MBAR_WAIT(smem_u32(&mbar[buf]), phs);

        // Refill immediately: target stage (buf+3)%4 == stage consumed LAST
        // iteration (its readers all passed that iteration's __syncthreads).
        // Keeps 3 chunks outstanding per block during the whole compute phase.
        if (tid == 0) {
            int ib = buf + (STAGES - 1);
            if (ib >= STAGES) ib -= STAGES;
            int cn = (int)atomicAdd(&g_ticket, 1u);
            s_chunk[ib] = cn;
            if (cn < NCHUNK) issue(cn, ib);
        }

        // Cell record as float2 (15 float2 per cell per tensor).
        const float2* p2 = (const float2*)(smem + buf * 2 * CHUNK_FLOATS + cell * F);
        const float2* t2 = (const float2*)((const float*)p2 + CHUNK_FLOATS);

        const float2 pc = p2[10];
        const float2 tc = t2[10];
        const bool obj = tc.x > 0.0f;

        // conf term (once per cell -> part 0); t[21] == t[20].
        if (part == 0) {
            float d0 = pc.x - tc.x, d1 = pc.y - tc.y;
            l += 0.5f * (d0 * d0 + d1 * d1);
        }

        const unsigned omask = __ballot_sync(0xffffffffu, obj);

        if (obj) {
            float acc = 0.0f;
#pragma unroll
            for (int j = 0; j < 5; j++) {
                float2 a = p2[5 * part + j], b = t2[5 * part + j];
                float dx = a.x - b.x, dy = a.y - b.y;
                acc += dx * dx + dy * dy;
            }
            l += acc;

            float2 pxy = p2[11 + 2 * part], pwh = p2[12 + 2 * part];
            float2 txy = t2[11 + 2 * part], twh = t2[12 + 2 * part];
            float xA = fmaxf(pxy.x - pwh.x * 0.5f, txy.x - twh.x * 0.5f);
            float yA = fmaxf(pxy.y - pwh.y * 0.5f, txy.y - twh.y * 0.5f);
            float xB = fminf(pxy.x + pwh.x * 0.5f, txy.x + twh.x * 0.5f);
            float yB = fminf(pxy.y + pwh.y * 0.5f, txy.y + twh.y * 0.5f);
            float inter = fmaxf(0.0f, xB - xA) * fmaxf(0.0f, yB - yA);
            float iou_mine = inter / (pwh.x * pwh.y + twh.x * twh.y - inter);

            float iou_other = __shfl_xor_sync(omask, iou_mine, 1);
            float iou0 = part ? iou_other : iou_mine;
            float iou1 = part ? iou_mine : iou_other;
            int best = (iou1 > iou0) ? 1 : 0;   // argmax, tie -> 0

            if (part == 0) {
                float pcv = best ? pc.y : pc.x;
                float dc = pcv - 1.0f;
                l += 0.5f * dc * dc;
            }

            if (best == part) {
                float dx = pxy.x - txy.x;
                float dy = pxy.y - txy.y;
                float dw = sqrtf(pwh.x) - sqrtf(twh.x);
                float dh = sqrtf(pwh.y) - sqrtf(twh.y);
                l += 5.0f * (dx * dx + dy * dy + dw * dw + dh * dh);
            }
        }

        __syncthreads();   // stage `buf` fully consumed; also publishes s_chunk

        if (++buf == STAGES) { buf = 0; phs ^= 1; }
    }

    // Intra-block reduction.
#pragma unroll
    for (int off = 16; off > 0; off >>= 1)
        l += __shfl_down_sync(0xffffffffu, l, off);
    if ((tid & 31) == 0)
        warp_sums[tid >> 5] = l;
    __syncthreads();

    if (tid == 0) {
        float blk = warp_sums[0] + warp_sums[1] + warp_sums[2] + warp_sums[3];
        g_partial[blockIdx.x] = blk;
        __threadfence();
        unsigned int old = atomicAdd(&g_count, 1u);
        is_last = (old == GRID - 1);
    }
    __syncthreads();

    if (is_last) {
        double acc = 0.0;
        for (int i = tid; i < GRID; i += THREADS)
            acc += (double)__ldcg(&g_partial[i]);
#pragma unroll
        for (int off = 16; off > 0; off >>= 1)
            acc += __shfl_down_sync(0xffffffffu, acc, off);
        if ((tid & 31) == 0)
            dsum[tid >> 5] = acc;
        __syncthreads();
        if (tid == 0) {
            double total = dsum[0] + dsum[1] + dsum[2] + dsum[3];
            out[0] = (float)(total / (double)N_IMG);
            __threadfence();
            g_count = 0;
            g_ticket = 0;   // reset scheduler for next graph replay
        }
    }
}

extern "C" void kernel_launch(void* const* d_in, const int* in_sizes, int n_in,
                              void* d_out, int out_size) {
    const float* preds = (const float*)d_in[0];
    const float* targets = (const float*)d_in[1];
    float* out = (float*)d_out;

    cudaFuncSetAttribute(loss_kernel, cudaFuncAttributeMaxDynamicSharedMemorySize, DYN_SMEM);
    loss_kernel<<<GRID, THREADS, DYN_SMEM>>>(preds, targets, out);
}

// round 9
// speedup vs baseline: 1.0065x; 1.0065x over previous
#include <cuda_runtime.h>
#include <cstdint>

// Problem constants
#define N_IMG 16384
#define SS 49
#define NCELL (N_IMG * SS)              // 802816
#define F 30                            // 20 probs + 2 conf + 8 box
#define CPC 128                         // cells per chunk
#define NCHUNK (NCELL / CPC)            // 6272
#define THREADS 128
#define GRID 444                        // 3 blocks/SM * 148 SMs
#define STAGES 2

#define CHUNK_FLOATS (CPC * F)          // 3840 floats
#define CHUNK_BYTES (CHUNK_FLOATS * 4)  // 15360 B per tensor
#define TX_BYTES (2 * CHUNK_BYTES)      // 30720 B per chunk
#define DYN_SMEM (STAGES * TX_BYTES)    // 61440 B

__device__ float g_partial[GRID];
__device__ unsigned int g_count;        // zero at load; last block resets each run

__device__ __forceinline__ uint32_t smem_u32(const void* p) {
    return (uint32_t)__cvta_generic_to_shared(p);
}

#define MBAR_WAIT(bar, parity) do {                                           \
    asm volatile(                                                             \
        "{\n\t.reg .pred P1;\n\t"                                             \
        "WAIT_%=:\n\t"                                                        \
        "mbarrier.try_wait.parity.acquire.cta.shared::cta.b64 P1, [%0], %1, 0x989680;\n\t" \
        "@P1 bra.uni DONE_%=;\n\t"                                            \
        "bra.uni WAIT_%=;\n\t"                                                \
        "DONE_%=:\n\t}"                                                       \
        :: "r"(bar), "r"(parity) : "memory");                                 \
} while (0)

__global__ __launch_bounds__(THREADS) void loss_kernel(
        const float* __restrict__ preds,
        const float* __restrict__ targets,
        float* __restrict__ out) {
    extern __shared__ float smem[];   // [STAGES][preds 3840 | targets 3840]
    __shared__ __align__(8) unsigned long long mbar[STAGES];
    __shared__ float warp_sums[THREADS / 32];
    __shared__ double dsum[THREADS / 32];
    __shared__ bool is_last;

    const int tid = threadIdx.x;

    if (tid == 0) {
#pragma unroll
        for (int s = 0; s < STAGES; s++)
            asm volatile("mbarrier.init.shared.b64 [%0], 1;"
                         :: "r"(smem_u32(&mbar[s])) : "memory");
    }
    __syncthreads();

    // Issue one chunk's loads (both tensors) into stage `buf`.
    auto issue = [&](int c, int buf) {
        uint32_t bar = smem_u32(&mbar[buf]);
        asm volatile("mbarrier.arrive.expect_tx.shared.b64 _, [%0], %1;"
                     :: "r"(bar), "r"((uint32_t)TX_BYTES) : "memory");
        uint32_t dstp = smem_u32(smem) + buf * TX_BYTES;
        uint32_t dstt = dstp + CHUNK_BYTES;
        const float* srcp = preds + (long long)c * CHUNK_FLOATS;
        const float* srct = targets + (long long)c * CHUNK_FLOATS;
        asm volatile("cp.async.bulk.shared::cta.global.mbarrier::complete_tx::bytes [%0], [%1], %2, [%3];"
                     :: "r"(dstp), "l"(srcp), "r"((uint32_t)CHUNK_BYTES), "r"(bar) : "memory");
        asm volatile("cp.async.bulk.shared::cta.global.mbarrier::complete_tx::bytes [%0], [%1], %2, [%3];"
                     :: "r"(dstt), "l"(srct), "r"((uint32_t)CHUNK_BYTES), "r"(bar) : "memory");
    };

    // Prefetch a future chunk's lines into L2 (keeps DRAM uniformly busy;
    // demand TMA later hits L2).
    auto prefetch_l2 = [&](int c) {
        const float* srcp = preds + (long long)c * CHUNK_FLOATS;
        const float* srct = targets + (long long)c * CHUNK_FLOATS;
        asm volatile("cp.async.bulk.prefetch.L2.global [%0], %1;"
                     :: "l"(srcp), "r"((uint32_t)CHUNK_BYTES) : "memory");
        asm volatile("cp.async.bulk.prefetch.L2.global [%0], %1;"
                     :: "l"(srct), "r"((uint32_t)CHUNK_BYTES) : "memory");
    };

    // Prologue: prefetch first two chunks (demand) + two more into L2.
    if (tid == 0) {
        if ((int)blockIdx.x < NCHUNK) issue(blockIdx.x, 0);
        if ((int)blockIdx.x + GRID < NCHUNK) issue(blockIdx.x + GRID, 1);
        if ((int)blockIdx.x + 2 * GRID < NCHUNK) prefetch_l2(blockIdx.x + 2 * GRID);
        if ((int)blockIdx.x + 3 * GRID < NCHUNK) prefetch_l2(blockIdx.x + 3 * GRID);
    }

    float l = 0.0f;
    int k = 0;
    for (int c = blockIdx.x; c < NCHUNK; c += GRID, k++) {
        const int buf = k & 1;
        const int phs = (k >> 1) & 1;

        // Issue L2 prefetch for the chunk 4 strides ahead (2 chunk-cycles of
        // lead time) BEFORE blocking on the mbarrier.
        int pf = c + 4 * GRID;
        if (tid == 0 && pf < NCHUNK) prefetch_l2(pf);

        MBAR_WAIT(smem_u32(&mbar[buf]), phs);

        const float* p = smem + buf * 2 * CHUNK_FLOATS + tid * F;
        const float* t = p + CHUNK_FLOATS;

        // conf MSE term (always): NOOBJ * sum((p_conf - t_conf)^2)
        float pc0 = p[20], pc1 = p[21];
        float tc0 = t[20], tc1 = t[21];
        float d0 = pc0 - tc0, d1 = pc1 - tc1;
        l += 0.5f * (d0 * d0 + d1 * d1);

        if (tc0 > 0.0f) {  // obj cell
            float s = 0.0f;
#pragma unroll
            for (int cc = 0; cc < 20; cc++) {
                float d = p[cc] - t[cc];
                s += d * d;
            }
            l += s;

            float iou0, iou1;
#pragma unroll
            for (int b = 0; b < 2; b++) {
                const float* pb = p + 22 + 4 * b;
                const float* tb = t + 22 + 4 * b;
                float xA = fmaxf(pb[0] - pb[2] * 0.5f, tb[0] - tb[2] * 0.5f);
                float yA = fmaxf(pb[1] - pb[3] * 0.5f, tb[1] - tb[3] * 0.5f);
                float xB = fminf(pb[0] + pb[2] * 0.5f, tb[0] + tb[2] * 0.5f);
                float yB = fminf(pb[1] + pb[3] * 0.5f, tb[1] + tb[3] * 0.5f);
                float inter = fmaxf(0.0f, xB - xA) * fmaxf(0.0f, yB - yA);
                float areaA = pb[2] * pb[3];
                float areaB = tb[2] * tb[3];
                float iou = inter / (areaA + areaB - inter);
                if (b == 0) iou0 = iou; else iou1 = iou;
            }
            int best = (iou1 > iou0) ? 1 : 0;  // argmax, tie -> index 0

            float pc = best ? pc1 : pc0;
            float dc = pc - 1.0f;
            l += 0.5f * dc * dc;

            const float* pb = p + 22 + 4 * best;
            const float* tb = t + 22 + 4 * best;
            float dx = pb[0] - tb[0];
            float dy = pb[1] - tb[1];
            float dw = sqrtf(pb[2]) - sqrtf(tb[2]);
            float dh = sqrtf(pb[3]) - sqrtf(tb[3]);
            l += 5.0f * (dx * dx + dy * dy + dw * dw + dh * dh);
        }

        __syncthreads();  // all threads done reading buffer `buf`

        int nx = c + 2 * GRID;
        if (tid == 0 && nx < NCHUNK) issue(nx, buf);
    }

    // Intra-block reduction.
#pragma unroll
    for (int off = 16; off > 0; off >>= 1)
        l += __shfl_down_sync(0xffffffffu, l, off);
    if ((tid & 31) == 0)
        warp_sums[tid >> 5] = l;
    __syncthreads();

    if (tid == 0) {
        float blk = warp_sums[0] + warp_sums[1] + warp_sums[2] + warp_sums[3];
        g_partial[blockIdx.x] = blk;
        __threadfence();
        unsigned int old = atomicAdd(&g_count, 1u);
        is_last = (old == GRID - 1);
    }
    __syncthreads();

    if (is_last) {
        double acc = 0.0;
        for (int i = tid; i < GRID; i += THREADS)
            acc += (double)__ldcg(&g_partial[i]);
#pragma unroll
        for (int off = 16; off > 0; off >>= 1)
            acc += __shfl_down_sync(0xffffffffu, acc, off);
        if ((tid & 31) == 0)
            dsum[tid >> 5] = acc;
        __syncthreads();
        if (tid == 0) {
            double total = dsum[0] + dsum[1] + dsum[2] + dsum[3];
            out[0] = (float)(total / (double)N_IMG);
            __threadfence();
            g_count = 0;  // reset for next graph replay
        }
    }
}

extern "C" void kernel_launch(void* const* d_in, const int* in_sizes, int n_in,
                              void* d_out, int out_size) {
    const float* preds = (const float*)d_in[0];
    const float* targets = (const float*)d_in[1];
    float* out = (float*)d_out;

    cudaFuncSetAttribute(loss_kernel, cudaFuncAttributeMaxDynamicSharedMemorySize, DYN_SMEM);
    loss_kernel<<<GRID, THREADS, DYN_SMEM>>>(preds, targets, out);
}

// round 10
// speedup vs baseline: 1.0727x; 1.0658x over previous
#include <cuda_runtime.h>
#include <cstdint>

// Problem constants
#define N_IMG 16384
#define SS 49
#define NCELL (N_IMG * SS)              // 802816
#define F 30                            // 20 probs + 2 conf + 8 box
#define CPC 128                         // cells per chunk
#define NCHUNK (NCELL / CPC)            // 6272
#define THREADS 128
#define GRID 392                        // 6272 / 392 = 16 chunks per block, exact
#define STAGES 2

#define CHUNK_FLOATS (CPC * F)          // 3840 floats
#define CHUNK_BYTES (CHUNK_FLOATS * 4)  // 15360 B per tensor
#define TX_BYTES (2 * CHUNK_BYTES)      // 30720 B per chunk
#define DYN_SMEM (STAGES * TX_BYTES)    // 61440 B

__device__ float g_partial[GRID];
__device__ unsigned int g_count;        // zero at load; last block resets each run

__device__ __forceinline__ uint32_t smem_u32(const void* p) {
    return (uint32_t)__cvta_generic_to_shared(p);
}

#define MBAR_WAIT(bar, parity) do {                                           \
    asm volatile(                                                             \
        "{\n\t.reg .pred P1;\n\t"                                             \
        "WAIT_%=:\n\t"                                                        \
        "mbarrier.try_wait.parity.acquire.cta.shared::cta.b64 P1, [%0], %1, 0x989680;\n\t" \
        "@P1 bra.uni DONE_%=;\n\t"                                            \
        "bra.uni WAIT_%=;\n\t"                                                \
        "DONE_%=:\n\t}"                                                       \
        :: "r"(bar), "r"(parity) : "memory");                                 \
} while (0)

__global__ __launch_bounds__(THREADS) void loss_kernel(
        const float* __restrict__ preds,
        const float* __restrict__ targets,
        float* __restrict__ out) {
    extern __shared__ float smem[];   // [STAGES][preds 3840 | targets 3840]
    __shared__ __align__(8) unsigned long long mbar[STAGES];
    __shared__ float warp_sums[THREADS / 32];
    __shared__ double dsum[THREADS / 32];
    __shared__ bool is_last;

    const int tid = threadIdx.x;

    if (tid == 0) {
#pragma unroll
        for (int s = 0; s < STAGES; s++)
            asm volatile("mbarrier.init.shared.b64 [%0], 1;"
                         :: "r"(smem_u32(&mbar[s])) : "memory");
    }
    __syncthreads();

    // Issue one chunk's loads (both tensors) into stage `buf`.
    auto issue = [&](int c, int buf) {
        uint32_t bar = smem_u32(&mbar[buf]);
        asm volatile("mbarrier.arrive.expect_tx.shared.b64 _, [%0], %1;"
                     :: "r"(bar), "r"((uint32_t)TX_BYTES) : "memory");
        uint32_t dstp = smem_u32(smem) + buf * TX_BYTES;
        uint32_t dstt = dstp + CHUNK_BYTES;
        const float* srcp = preds + (long long)c * CHUNK_FLOATS;
        const float* srct = targets + (long long)c * CHUNK_FLOATS;
        asm volatile("cp.async.bulk.shared::cta.global.mbarrier::complete_tx::bytes [%0], [%1], %2, [%3];"
                     :: "r"(dstp), "l"(srcp), "r"((uint32_t)CHUNK_BYTES), "r"(bar) : "memory");
        asm volatile("cp.async.bulk.shared::cta.global.mbarrier::complete_tx::bytes [%0], [%1], %2, [%3];"
                     :: "r"(dstt), "l"(srct), "r"((uint32_t)CHUNK_BYTES), "r"(bar) : "memory");
    };

    // Prologue: prefetch first two chunks.
    if (tid == 0) {
        issue(blockIdx.x, 0);
        issue(blockIdx.x + GRID, 1);
    }

    float l = 0.0f;
    int k = 0;
    for (int c = blockIdx.x; c < NCHUNK; c += GRID, k++) {   // exactly 16 iters/block
        const int buf = k & 1;
        const int phs = (k >> 1) & 1;
        MBAR_WAIT(smem_u32(&mbar[buf]), phs);

        const float* p = smem + buf * 2 * CHUNK_FLOATS + tid * F;
        const float* t = p + CHUNK_FLOATS;

        // conf MSE term (always): NOOBJ * sum((p_conf - t_conf)^2)
        float pc0 = p[20], pc1 = p[21];
        float tc0 = t[20], tc1 = t[21];
        float d0 = pc0 - tc0, d1 = pc1 - tc1;
        l += 0.5f * (d0 * d0 + d1 * d1);

        if (tc0 > 0.0f) {  // obj cell
            float s = 0.0f;
#pragma unroll
            for (int cc = 0; cc < 20; cc++) {
                float d = p[cc] - t[cc];
                s += d * d;
            }
            l += s;

            float iou0, iou1;
#pragma unroll
            for (int b = 0; b < 2; b++) {
                const float* pb = p + 22 + 4 * b;
                const float* tb = t + 22 + 4 * b;
                float xA = fmaxf(pb[0] - pb[2] * 0.5f, tb[0] - tb[2] * 0.5f);
                float yA = fmaxf(pb[1] - pb[3] * 0.5f, tb[1] - tb[3] * 0.5f);
                float xB = fminf(pb[0] + pb[2] * 0.5f, tb[0] + tb[2] * 0.5f);
                float yB = fminf(pb[1] + pb[3] * 0.5f, tb[1] + tb[3] * 0.5f);
                float inter = fmaxf(0.0f, xB - xA) * fmaxf(0.0f, yB - yA);
                float areaA = pb[2] * pb[3];
                float areaB = tb[2] * tb[3];
                float iou = inter / (areaA + areaB - inter);
                if (b == 0) iou0 = iou; else iou1 = iou;
            }
            int best = (iou1 > iou0) ? 1 : 0;  // argmax, tie -> index 0

            float pc = best ? pc1 : pc0;
            float dc = pc - 1.0f;
            l += 0.5f * dc * dc;

            const float* pb = p + 22 + 4 * best;
            const float* tb = t + 22 + 4 * best;
            float dx = pb[0] - tb[0];
            float dy = pb[1] - tb[1];
            float dw = sqrtf(pb[2]) - sqrtf(tb[2]);
            float dh = sqrtf(pb[3]) - sqrtf(tb[3]);
            l += 5.0f * (dx * dx + dy * dy + dw * dw + dh * dh);
        }

        __syncthreads();  // all threads done reading buffer `buf`

        int nx = c + 2 * GRID;
        if (tid == 0 && nx < NCHUNK) issue(nx, buf);
    }

    // Intra-block reduction.
#pragma unroll
    for (int off = 16; off > 0; off >>= 1)
        l += __shfl_down_sync(0xffffffffu, l, off);
    if ((tid & 31) == 0)
        warp_sums[tid >> 5] = l;
    __syncthreads();

    if (tid == 0) {
        float blk = warp_sums[0] + warp_sums[1] + warp_sums[2] + warp_sums[3];
        g_partial[blockIdx.x] = blk;
        __threadfence();
        unsigned int old = atomicAdd(&g_count, 1u);
        is_last = (old == GRID - 1);
    }
    __syncthreads();

    if (is_last) {
        double acc = 0.0;
        for (int i = tid; i < GRID; i += THREADS)
            acc += (double)__ldcg(&g_partial[i]);
#pragma unroll
        for (int off = 16; off > 0; off >>= 1)
            acc += __shfl_down_sync(0xffffffffu, acc, off);
        if ((tid & 31) == 0)
            dsum[tid >> 5] = acc;
        __syncthreads();
        if (tid == 0) {
            double total = dsum[0] + dsum[1] + dsum[2] + dsum[3];
            out[0] = (float)(total / (double)N_IMG);
            __threadfence();
            g_count = 0;  // reset for next graph replay
        }
    }
}

extern "C" void kernel_launch(void* const* d_in, const int* in_sizes, int n_in,
                              void* d_out, int out_size) {
    const float* preds = (const float*)d_in[0];
    const float* targets = (const float*)d_in[1];
    float* out = (float*)d_out;

    cudaFuncSetAttribute(loss_kernel, cudaFuncAttributeMaxDynamicSharedMemorySize, DYN_SMEM);
    loss_kernel<<<GRID, THREADS, DYN_SMEM>>>(preds, targets, out);
}